// round 11
// baseline (speedup 1.0000x reference)
#include <cuda_runtime.h>
#include <cuda_bf16.h>
#include <cstdint>

#define BATCH 8
#define SEQ 512
#define DM 512
#define NELEM (BATCH*SEQ*DM)

// ============================ scratch (bf16 hi/lo splits) ============================
__device__ __align__(16) __nv_bfloat16 g_Qhi[NELEM];
__device__ __align__(16) __nv_bfloat16 g_Qlo[NELEM];
__device__ __align__(16) __nv_bfloat16 g_QRhi[NELEM];
__device__ __align__(16) __nv_bfloat16 g_QRlo[NELEM];
__device__ __align__(16) __nv_bfloat16 g_Khi[NELEM];
__device__ __align__(16) __nv_bfloat16 g_Klo[NELEM];
__device__ __align__(16) __nv_bfloat16 g_Ethi[DM*DM];
__device__ __align__(16) __nv_bfloat16 g_Etlo[DM*DM];

__device__ __forceinline__ void split_bf16(float x, __nv_bfloat16& h, __nv_bfloat16& l) {
    h = __float2bfloat16(x);
    l = __float2bfloat16(x - __bfloat162float(h));
}

__device__ __forceinline__ uint32_t smem_u32(const void* p) {
    uint32_t a;
    asm("{ .reg .u64 t; cvta.to.shared.u64 t, %1; cvt.u32.u64 %0, t; }" : "=r"(a) : "l"(p));
    return a;
}

// ============================ fused prep kernel ============================
#define QBLOCKS (BATCH*SEQ)
#define KBLOCKS 2048
#define EBLOCKS 256

__global__ void prep_all_kernel(const float* __restrict__ q,
                                const float* __restrict__ k,
                                const float* __restrict__ e) {
    __shared__ float sh[32 * 33 + 128];
    int bid = blockIdx.x;
    int t = threadIdx.x;                  // 128 threads

    if (bid < QBLOCKS) {
        float* row = sh;
        float* red = sh + 512;
        int i = bid & (SEQ - 1);
        const float4* src = reinterpret_cast<const float4*>(q + (size_t)bid * DM);
        reinterpret_cast<float4*>(row)[t] = src[t];
        __syncthreads();

        float p = 0.f;
        #pragma unroll
        for (int j = t; j < DM; j += 128)
            if (j >= i) p += row[j];
        red[t] = p;
        __syncthreads();
        #pragma unroll
        for (int s = 64; s > 0; s >>= 1) {
            if (t < s) red[t] += red[t + s];
            __syncthreads();
        }
        float suf = red[0];

        size_t base = (size_t)bid * DM;
        #pragma unroll
        for (int d = t; d < DM; d += 128) {
            float x = row[d];
            split_bf16(x, g_Qhi[base + d], g_Qlo[base + d]);
            float r = (d == 0) ? suf : ((d <= i) ? row[i - d] : 0.f);
            split_bf16(r, g_QRhi[base + d], g_QRlo[base + d]);
        }
    } else if (bid < QBLOCKS + KBLOCKS) {
        int idx = (bid - QBLOCKS) * 128 + t;
        int n4 = NELEM / 4;
        int stride = KBLOCKS * 128;
        for (int j = idx; j < n4; j += stride) {
            float4 v = reinterpret_cast<const float4*>(k)[j];
            __nv_bfloat16 h[4], l[4];
            split_bf16(v.x, h[0], l[0]);
            split_bf16(v.y, h[1], l[1]);
            split_bf16(v.z, h[2], l[2]);
            split_bf16(v.w, h[3], l[3]);
            reinterpret_cast<uint2*>(g_Khi)[j] = *reinterpret_cast<uint2*>(h);
            reinterpret_cast<uint2*>(g_Klo)[j] = *reinterpret_cast<uint2*>(l);
        }
    } else {
        float (*tile)[33] = reinterpret_cast<float(*)[33]>(sh);
        int eb = bid - QBLOCKS - KBLOCKS;
        int bx = eb & 15, by = eb >> 4;
        int tx = t & 31, j0 = t >> 5;
        #pragma unroll
        for (int j = j0; j < 32; j += 4)
            tile[j][tx] = e[(size_t)(by * 32 + j) * DM + bx * 32 + tx];
        __syncthreads();
        #pragma unroll
        for (int j = j0; j < 32; j += 4) {
            size_t o = (size_t)(bx * 32 + j) * DM + by * 32 + tx;
            split_bf16(tile[tx][j], g_Ethi[o], g_Etlo[o]);
        }
    }
}

// ============================ main GEMM (mma.sync bf16) ============================
// 128x128 CTA tile, 512 threads (4x4 warps, 32x32 warp tiles), 3-stage cp.async,
// register-double-buffered fragments: ldmatrix for k16+1 issued before MMAs of k16
// so LSU/crossbar time hides under tensor work.
// Pass 1 (Qrev.Et) skips all-zero K-chunks: tile at m0=128*by needs 2*by+2 of 8.

#define BM 128
#define BN 128
#define BK 64
#define THREADS 512
#define TILE_HB (BM * BK * 2)               // 16384 per hi or lo tile
#define STAGE_B (4 * TILE_HB)               // 65536: Ahi,Alo,Bhi,Blo
#define NSTAGE 3
#define SMEM_TOTAL (NSTAGE * STAGE_B)       // 196608

#define OFF_AH 0
#define OFF_AL TILE_HB
#define OFF_BH (2 * TILE_HB)
#define OFF_BL (3 * TILE_HB)

__device__ __forceinline__ uint32_t sw_off(int row, int kk) {
    return (uint32_t)(row * 128 + (((kk >> 3) ^ (row & 7)) << 4) + ((kk & 7) << 1));
}

__device__ __forceinline__ void cp_async16(uint32_t saddr, const void* gaddr) {
    asm volatile("cp.async.cg.shared.global [%0], [%1], 16;" :: "r"(saddr), "l"(gaddr));
}

__device__ __forceinline__ void ldmatrix_x4(uint32_t& r0, uint32_t& r1, uint32_t& r2,
                                            uint32_t& r3, uint32_t addr) {
    asm volatile("ldmatrix.sync.aligned.m8n8.x4.shared.b16 {%0,%1,%2,%3}, [%4];"
                 : "=r"(r0), "=r"(r1), "=r"(r2), "=r"(r3) : "r"(addr));
}

__device__ __forceinline__ void mma16816(float* c, const uint32_t* a, uint32_t b0, uint32_t b1) {
    asm volatile(
        "mma.sync.aligned.m16n8k16.row.col.f32.bf16.bf16.f32 "
        "{%0,%1,%2,%3}, {%4,%5,%6,%7}, {%8,%9}, {%0,%1,%2,%3};"
        : "+f"(c[0]), "+f"(c[1]), "+f"(c[2]), "+f"(c[3])
        : "r"(a[0]), "r"(a[1]), "r"(a[2]), "r"(a[3]), "r"(b0), "r"(b1));
}

__global__ __launch_bounds__(THREADS, 1) void rel_gemm_kernel(float* __restrict__ out) {
    extern __shared__ char smem[];
    uint32_t sb = smem_u32(smem);

    int tid = threadIdx.x;
    int lane = tid & 31, wid = tid >> 5;
    int wm = wid & 3, wn = wid >> 2;          // 4 m-warps x 4 n-warps, warp tile 32x32
    int n0 = blockIdx.x * BN;
    int m0 = blockIdx.y * BM;
    int b  = blockIdx.z;
    size_t boff = (size_t)b * SEQ * DM;

    // chunks: [0,8) pass 0 (Q.K), [8, 10+2*by) pass 1 (Qrev.Et nonzero prefix)
    int total = 10 + 2 * (int)blockIdx.y;

    const __nv_bfloat16* AH[2] = { g_Qhi + boff, g_QRhi + boff };
    const __nv_bfloat16* AL[2] = { g_Qlo + boff, g_QRlo + boff };
    const __nv_bfloat16* BH[2] = { g_Khi + boff, g_Ethi };
    const __nv_bfloat16* BL[2] = { g_Klo + boff, g_Etlo };

    // precomputed per-lane ldmatrix row/col pieces
    int a_row = wm * 32 + (lane & 7) + ((lane >> 3) & 1) * 8;   // + mi*16
    int a_kk  = (lane >> 4) << 3;                               // + kc
    int b_row = wn * 32 + (lane & 7) + ((lane >> 4) << 3);      // + nb*16
    int b_kk  = ((lane >> 3) & 1) << 3;                         // + kc

    float acc[2][4][4];
    #pragma unroll
    for (int mi = 0; mi < 2; mi++)
        #pragma unroll
        for (int ni = 0; ni < 4; ni++)
            #pragma unroll
            for (int j = 0; j < 4; j++) acc[mi][ni][j] = 0.f;

    // double-buffered fragments
    uint32_t ah[2][2][4], al[2][2][4], bh[2][2][4], bl[2][2][4];

    auto load_chunk = [&](int it) {
        int pass = it >> 3, kc = it & 7;
        const __nv_bfloat16* pah = AH[pass] + (size_t)m0 * DM + kc * BK;
        const __nv_bfloat16* pal = AL[pass] + (size_t)m0 * DM + kc * BK;
        const __nv_bfloat16* pbh = BH[pass] + (size_t)n0 * DM + kc * BK;
        const __nv_bfloat16* pbl = BL[pass] + (size_t)n0 * DM + kc * BK;
        uint32_t st = sb + (it % NSTAGE) * STAGE_B;
        #pragma unroll
        for (int r2 = 0; r2 < 2; r2++) {          // 128 rows x 8 16B-chunks = 1024
            int idx = tid + r2 * THREADS;
            int row = idx >> 3, ck = idx & 7;
            uint32_t so = (uint32_t)(row * 128 + ((ck ^ (row & 7)) << 4));
            cp_async16(st + OFF_AH + so, pah + row * DM + ck * 8);
            cp_async16(st + OFF_AL + so, pal + row * DM + ck * 8);
            cp_async16(st + OFF_BH + so, pbh + row * DM + ck * 8);
            cp_async16(st + OFF_BL + so, pbl + row * DM + ck * 8);
        }
        asm volatile("cp.async.commit_group;");
    };

    auto ld_frags = [&](int k16, int buf, uint32_t st) {
        int kc = k16 * 16;
        #pragma unroll
        for (int mi = 0; mi < 2; mi++) {
            uint32_t so = sw_off(a_row + mi * 16, a_kk + kc);
            ldmatrix_x4(ah[buf][mi][0], ah[buf][mi][1], ah[buf][mi][2], ah[buf][mi][3],
                        st + OFF_AH + so);
            ldmatrix_x4(al[buf][mi][0], al[buf][mi][1], al[buf][mi][2], al[buf][mi][3],
                        st + OFF_AL + so);
        }
        #pragma unroll
        for (int nb = 0; nb < 2; nb++) {
            uint32_t so = sw_off(b_row + nb * 16, b_kk + kc);
            ldmatrix_x4(bh[buf][nb][0], bh[buf][nb][1], bh[buf][nb][2], bh[buf][nb][3],
                        st + OFF_BH + so);
            ldmatrix_x4(bl[buf][nb][0], bl[buf][nb][1], bl[buf][nb][2], bl[buf][nb][3],
                        st + OFF_BL + so);
        }
    };

    auto mma_all = [&](int buf) {
        #pragma unroll
        for (int mi = 0; mi < 2; mi++)            // hi*hi
            #pragma unroll
            for (int nb = 0; nb < 2; nb++)
                #pragma unroll
                for (int h = 0; h < 2; h++)
                    mma16816(acc[mi][nb * 2 + h], ah[buf][mi],
                             bh[buf][nb][2 * h], bh[buf][nb][2 * h + 1]);
        #pragma unroll
        for (int mi = 0; mi < 2; mi++)            // hi*lo
            #pragma unroll
            for (int nb = 0; nb < 2; nb++)
                #pragma unroll
                for (int h = 0; h < 2; h++)
                    mma16816(acc[mi][nb * 2 + h], ah[buf][mi],
                             bl[buf][nb][2 * h], bl[buf][nb][2 * h + 1]);
        #pragma unroll
        for (int mi = 0; mi < 2; mi++)            // lo*hi
            #pragma unroll
            for (int nb = 0; nb < 2; nb++)
                #pragma unroll
                for (int h = 0; h < 2; h++)
                    mma16816(acc[mi][nb * 2 + h], al[buf][mi],
                             bh[buf][nb][2 * h], bh[buf][nb][2 * h + 1]);
    };

    load_chunk(0);
    if (total > 1) load_chunk(1);

    for (int it = 0; it < total; it++) {
        asm volatile("cp.async.wait_group 1;");   // load(it) complete; load(it+1) may pend
        __syncthreads();                          // stage (it+2)%NSTAGE free of readers
        if (it + 2 < total) load_chunk(it + 2);

        uint32_t st = sb + (it % NSTAGE) * STAGE_B;

        // software-pipelined fragment loop: LDSM(k16+1) issued before MMA(k16)
        ld_frags(0, 0, st);
        #pragma unroll
        for (int k16 = 0; k16 < 4; k16++) {
            if (k16 < 3) ld_frags(k16 + 1, (k16 + 1) & 1, st);
            mma_all(k16 & 1);
        }
    }

    // epilogue
    int qr = lane >> 2, qc = (lane & 3) << 1;
    #pragma unroll
    for (int mi = 0; mi < 2; mi++) {
        int r0 = m0 + wm * 32 + mi * 16 + qr;
        #pragma unroll
        for (int ni = 0; ni < 4; ni++) {
            int c = n0 + wn * 32 + ni * 8 + qc;
            float* o0 = out + ((size_t)b * SEQ + r0) * DM + c;
            float* o1 = o0 + 8 * DM;
            *reinterpret_cast<float2*>(o0) = make_float2(acc[mi][ni][0], acc[mi][ni][1]);
            *reinterpret_cast<float2*>(o1) = make_float2(acc[mi][ni][2], acc[mi][ni][3]);
        }
    }
}

// ============================ launch ============================
extern "C" void kernel_launch(void* const* d_in, const int* in_sizes, int n_in,
                              void* d_out, int out_size) {
    const float* q = (const float*)d_in[0];
    const float* k = (const float*)d_in[1];
    const float* e = (const float*)d_in[2];
    float* out = (float*)d_out;

    cudaFuncSetAttribute(rel_gemm_kernel,
                         cudaFuncAttributeMaxDynamicSharedMemorySize, SMEM_TOTAL);

    prep_all_kernel<<<QBLOCKS + KBLOCKS + EBLOCKS, 128>>>(q, k, e);
    rel_gemm_kernel<<<dim3(SEQ / BN, SEQ / BM, BATCH), THREADS, SMEM_TOTAL>>>(out);
}

// round 13
// speedup vs baseline: 1.0862x; 1.0862x over previous
#include <cuda_runtime.h>
#include <cuda_bf16.h>
#include <cstdint>

#define BATCH 8
#define SEQ 512
#define DM 512
#define NELEM (BATCH*SEQ*DM)

// ============================ scratch (bf16 hi/lo splits) ============================
__device__ __align__(16) __nv_bfloat16 g_Qhi[NELEM];
__device__ __align__(16) __nv_bfloat16 g_Qlo[NELEM];
__device__ __align__(16) __nv_bfloat16 g_QRhi[NELEM];
__device__ __align__(16) __nv_bfloat16 g_QRlo[NELEM];
__device__ __align__(16) __nv_bfloat16 g_Khi[NELEM];
__device__ __align__(16) __nv_bfloat16 g_Klo[NELEM];
__device__ __align__(16) __nv_bfloat16 g_Ethi[DM*DM];
__device__ __align__(16) __nv_bfloat16 g_Etlo[DM*DM];

__device__ __forceinline__ void split_bf16(float x, __nv_bfloat16& h, __nv_bfloat16& l) {
    h = __float2bfloat16(x);
    l = __float2bfloat16(x - __bfloat162float(h));
}

__device__ __forceinline__ uint32_t smem_u32(const void* p) {
    uint32_t a;
    asm("{ .reg .u64 t; cvta.to.shared.u64 t, %1; cvt.u32.u64 %0, t; }" : "=r"(a) : "l"(p));
    return a;
}

// ============================ fused prep kernel ============================
#define QBLOCKS (BATCH*SEQ)
#define KBLOCKS 2048
#define EBLOCKS 256

__global__ void prep_all_kernel(const float* __restrict__ q,
                                const float* __restrict__ k,
                                const float* __restrict__ e) {
    __shared__ float sh[32 * 33 + 128];
    int bid = blockIdx.x;
    int t = threadIdx.x;                  // 128 threads

    if (bid < QBLOCKS) {
        float* row = sh;
        float* red = sh + 512;
        int i = bid & (SEQ - 1);
        const float4* src = reinterpret_cast<const float4*>(q + (size_t)bid * DM);
        reinterpret_cast<float4*>(row)[t] = src[t];
        __syncthreads();

        float p = 0.f;
        #pragma unroll
        for (int j = t; j < DM; j += 128)
            if (j >= i) p += row[j];
        red[t] = p;
        __syncthreads();
        #pragma unroll
        for (int s = 64; s > 0; s >>= 1) {
            if (t < s) red[t] += red[t + s];
            __syncthreads();
        }
        float suf = red[0];

        size_t base = (size_t)bid * DM;
        #pragma unroll
        for (int d = t; d < DM; d += 128) {
            float x = row[d];
            split_bf16(x, g_Qhi[base + d], g_Qlo[base + d]);
            float r = (d == 0) ? suf : ((d <= i) ? row[i - d] : 0.f);
            split_bf16(r, g_QRhi[base + d], g_QRlo[base + d]);
        }
    } else if (bid < QBLOCKS + KBLOCKS) {
        int idx = (bid - QBLOCKS) * 128 + t;
        int n4 = NELEM / 4;
        int stride = KBLOCKS * 128;
        for (int j = idx; j < n4; j += stride) {
            float4 v = reinterpret_cast<const float4*>(k)[j];
            __nv_bfloat16 h[4], l[4];
            split_bf16(v.x, h[0], l[0]);
            split_bf16(v.y, h[1], l[1]);
            split_bf16(v.z, h[2], l[2]);
            split_bf16(v.w, h[3], l[3]);
            reinterpret_cast<uint2*>(g_Khi)[j] = *reinterpret_cast<uint2*>(h);
            reinterpret_cast<uint2*>(g_Klo)[j] = *reinterpret_cast<uint2*>(l);
        }
    } else {
        float (*tile)[33] = reinterpret_cast<float(*)[33]>(sh);
        int eb = bid - QBLOCKS - KBLOCKS;
        int bx = eb & 15, by = eb >> 4;
        int tx = t & 31, j0 = t >> 5;
        #pragma unroll
        for (int j = j0; j < 32; j += 4)
            tile[j][tx] = e[(size_t)(by * 32 + j) * DM + bx * 32 + tx];
        __syncthreads();
        #pragma unroll
        for (int j = j0; j < 32; j += 4) {
            size_t o = (size_t)(bx * 32 + j) * DM + by * 32 + tx;
            split_bf16(tile[tx][j], g_Ethi[o], g_Etlo[o]);
        }
    }
}

// ============================ main GEMM: warp-specialized producer/consumer ============================
// 128x128 CTA tile. 384 threads: warps 0-7 consumers (4x2, warp tile 32x64),
// warps 8-11 producers (cp.async only). 3-stage mbarrier pipeline.
// Consumers never issue loads and never __syncthreads in the mainloop.
// Pass 1 (Qrev.Et) skips all-zero K-chunks: tile at m0=128*by needs 2*by+2 of 8.

#define BM 128
#define BN 128
#define BK 64
#define THREADS 384
#define NCONS 256                            // consumer threads
#define TILE_HB (BM * BK * 2)                // 16384 per hi/lo tile
#define STAGE_B (4 * TILE_HB)                // 65536: Ahi,Alo,Bhi,Blo
#define NSTAGE 3
#define MBAR_OFF (NSTAGE * STAGE_B)          // barriers after tiles
#define SMEM_TOTAL (MBAR_OFF + 64)           // 6 mbarriers (48B) + pad

#define OFF_AH 0
#define OFF_AL TILE_HB
#define OFF_BH (2 * TILE_HB)
#define OFF_BL (3 * TILE_HB)

__device__ __forceinline__ uint32_t sw_off(int row, int kk) {
    return (uint32_t)(row * 128 + (((kk >> 3) ^ (row & 7)) << 4) + ((kk & 7) << 1));
}

__device__ __forceinline__ void cp_async16(uint32_t saddr, const void* gaddr) {
    asm volatile("cp.async.cg.shared.global [%0], [%1], 16;" :: "r"(saddr), "l"(gaddr));
}

#define MBARRIER_INIT(addr, count) \
    asm volatile("mbarrier.init.shared.b64 [%0], %1;" :: "r"((uint32_t)(addr)), "r"((uint32_t)(count)) : "memory")

#define MBARRIER_ARRIVE(addr) \
    asm volatile("mbarrier.arrive.shared.b64 _, [%0];" :: "r"((uint32_t)(addr)) : "memory")

// .noinc: expected arrival count stays at the init value (128 producer threads);
// the default (incrementing) form double-counts and deadlocks.
#define CPASYNC_MBARRIER_ARRIVE_NOINC(addr) \
    asm volatile("cp.async.mbarrier.arrive.noinc.shared.b64 [%0];" :: "r"((uint32_t)(addr)) : "memory")

#define MBARRIER_WAIT_PARITY(addr, parity) do { \
    uint32_t _m = (uint32_t)(addr), _p = (uint32_t)(parity), _d; \
    asm volatile( \
        "{\n\t.reg .pred p;\n\t" \
        "mbarrier.try_wait.parity.shared.b64 p, [%1], %2;\n\t" \
        "selp.b32 %0, 1, 0, p;\n\t}" \
        : "=r"(_d) : "r"(_m), "r"(_p) : "memory"); \
    if (!_d) { \
        asm volatile( \
            "{\n\t.reg .pred P1;\n\t" \
            "WL_%=:\n\t" \
            "mbarrier.try_wait.parity.shared.b64 P1, [%0], %1;\n\t" \
            "@P1 bra.uni WD_%=;\n\t" \
            "bra.uni WL_%=;\n\t" \
            "WD_%=:\n\t}" \
            :: "r"(_m), "r"(_p) : "memory"); \
    } \
} while(0)

__device__ __forceinline__ void ldmatrix_x4(uint32_t& r0, uint32_t& r1, uint32_t& r2,
                                            uint32_t& r3, uint32_t addr) {
    asm volatile("ldmatrix.sync.aligned.m8n8.x4.shared.b16 {%0,%1,%2,%3}, [%4];"
                 : "=r"(r0), "=r"(r1), "=r"(r2), "=r"(r3) : "r"(addr));
}

__device__ __forceinline__ void mma16816(float* c, const uint32_t* a, uint32_t b0, uint32_t b1) {
    asm volatile(
        "mma.sync.aligned.m16n8k16.row.col.f32.bf16.bf16.f32 "
        "{%0,%1,%2,%3}, {%4,%5,%6,%7}, {%8,%9}, {%0,%1,%2,%3};"
        : "+f"(c[0]), "+f"(c[1]), "+f"(c[2]), "+f"(c[3])
        : "r"(a[0]), "r"(a[1]), "r"(a[2]), "r"(a[3]), "r"(b0), "r"(b1));
}

__global__ __launch_bounds__(THREADS, 1) void rel_gemm_kernel(float* __restrict__ out) {
    extern __shared__ char smem[];
    uint32_t sb = smem_u32(smem);
    uint32_t mb_full  = sb + MBAR_OFF;        // 3 x 8B
    uint32_t mb_empty = sb + MBAR_OFF + 24;   // 3 x 8B

    int tid = threadIdx.x;
    int lane = tid & 31, wid = tid >> 5;
    int n0 = blockIdx.x * BN;
    int m0 = blockIdx.y * BM;
    int b  = blockIdx.z;
    size_t boff = (size_t)b * SEQ * DM;
    int total = 10 + 2 * (int)blockIdx.y;     // pass0: 8 chunks, pass1: 2*by+2

    const __nv_bfloat16* AH[2] = { g_Qhi + boff, g_QRhi + boff };
    const __nv_bfloat16* AL[2] = { g_Qlo + boff, g_QRlo + boff };
    const __nv_bfloat16* BH[2] = { g_Khi + boff, g_Ethi };
    const __nv_bfloat16* BL[2] = { g_Klo + boff, g_Etlo };

    if (tid == 0) {
        #pragma unroll
        for (int s = 0; s < NSTAGE; s++) {
            MBARRIER_INIT(mb_full + s * 8, 128);    // 128 producer threads (.noinc arrive)
            MBARRIER_INIT(mb_empty + s * 8, NCONS); // 256 consumer threads
        }
    }
    __syncthreads();

    if (wid >= 8) {
        // ================= producers (warps 8-11, 128 threads) =================
        int ptid = tid - NCONS;               // 0..127
        for (int c = 0; c < total; c++) {
            int s = c % NSTAGE, f = c / NSTAGE;
            if (f >= 1) MBARRIER_WAIT_PARITY(mb_empty + s * 8, (f - 1) & 1);
            int pass = c >> 3, kc = c & 7;
            const __nv_bfloat16* pah = AH[pass] + (size_t)m0 * DM + kc * BK;
            const __nv_bfloat16* pal = AL[pass] + (size_t)m0 * DM + kc * BK;
            const __nv_bfloat16* pbh = BH[pass] + (size_t)n0 * DM + kc * BK;
            const __nv_bfloat16* pbl = BL[pass] + (size_t)n0 * DM + kc * BK;
            uint32_t st = sb + s * STAGE_B;
            #pragma unroll
            for (int r2 = 0; r2 < 8; r2++) {  // 128 thr x 8 iters = 1024 per tile
                int idx = ptid + r2 * 128;
                int row = idx >> 3, ck = idx & 7;
                uint32_t so = (uint32_t)(row * 128 + ((ck ^ (row & 7)) << 4));
                cp_async16(st + OFF_AH + so, pah + row * DM + ck * 8);
                cp_async16(st + OFF_AL + so, pal + row * DM + ck * 8);
                cp_async16(st + OFF_BH + so, pbh + row * DM + ck * 8);
                cp_async16(st + OFF_BL + so, pbl + row * DM + ck * 8);
            }
            CPASYNC_MBARRIER_ARRIVE_NOINC(mb_full + s * 8);
        }
        return;
    }

    // ================= consumers (warps 0-7, warp tile 32x64) =================
    int wm = wid & 3, wn = wid >> 2;          // 4 m-warps x 2 n-warps
    int a_row = wm * 32 + (lane & 7) + ((lane >> 3) & 1) * 8;   // + mi*16
    int a_kk  = (lane >> 4) << 3;                               // + kc
    int b_row = wn * 64 + (lane & 7) + ((lane >> 4) << 3);      // + nb*16
    int b_kk  = ((lane >> 3) & 1) << 3;                         // + kc

    float acc[2][8][4];
    #pragma unroll
    for (int mi = 0; mi < 2; mi++)
        #pragma unroll
        for (int ni = 0; ni < 8; ni++)
            #pragma unroll
            for (int j = 0; j < 4; j++) acc[mi][ni][j] = 0.f;

    for (int c = 0; c < total; c++) {
        int s = c % NSTAGE, f = c / NSTAGE;
        MBARRIER_WAIT_PARITY(mb_full + s * 8, f & 1);
        uint32_t st = sb + s * STAGE_B;

        #pragma unroll
        for (int k16 = 0; k16 < 4; k16++) {
            int kc = k16 * 16;
            uint32_t ah[2][4], al[2][4];
            #pragma unroll
            for (int mi = 0; mi < 2; mi++) {
                uint32_t so = sw_off(a_row + mi * 16, a_kk + kc);
                ldmatrix_x4(ah[mi][0], ah[mi][1], ah[mi][2], ah[mi][3], st + OFF_AH + so);
                ldmatrix_x4(al[mi][0], al[mi][1], al[mi][2], al[mi][3], st + OFF_AL + so);
            }
            uint32_t bh[4][4], bl[4][4];
            #pragma unroll
            for (int nb = 0; nb < 4; nb++) {
                uint32_t so = sw_off(b_row + nb * 16, b_kk + kc);
                ldmatrix_x4(bh[nb][0], bh[nb][1], bh[nb][2], bh[nb][3], st + OFF_BH + so);
                ldmatrix_x4(bl[nb][0], bl[nb][1], bl[nb][2], bl[nb][3], st + OFF_BL + so);
            }
            #pragma unroll
            for (int mi = 0; mi < 2; mi++)            // hi*hi
                #pragma unroll
                for (int nb = 0; nb < 4; nb++)
                    #pragma unroll
                    for (int h = 0; h < 2; h++)
                        mma16816(acc[mi][nb * 2 + h], ah[mi],
                                 bh[nb][2 * h], bh[nb][2 * h + 1]);
            #pragma unroll
            for (int mi = 0; mi < 2; mi++)            // hi*lo
                #pragma unroll
                for (int nb = 0; nb < 4; nb++)
                    #pragma unroll
                    for (int h = 0; h < 2; h++)
                        mma16816(acc[mi][nb * 2 + h], ah[mi],
                                 bl[nb][2 * h], bl[nb][2 * h + 1]);
            #pragma unroll
            for (int mi = 0; mi < 2; mi++)            // lo*hi
                #pragma unroll
                for (int nb = 0; nb < 4; nb++)
                    #pragma unroll
                    for (int h = 0; h < 2; h++)
                        mma16816(acc[mi][nb * 2 + h], al[mi],
                                 bh[nb][2 * h], bh[nb][2 * h + 1]);
        }
        MBARRIER_ARRIVE(mb_empty + s * 8);
    }

    // epilogue (consumers only)
    int qr = lane >> 2, qc = (lane & 3) << 1;
    #pragma unroll
    for (int mi = 0; mi < 2; mi++) {
        int r0 = m0 + wm * 32 + mi * 16 + qr;
        #pragma unroll
        for (int ni = 0; ni < 8; ni++) {
            int cidx = n0 + wn * 64 + ni * 8 + qc;
            float* o0 = out + ((size_t)b * SEQ + r0) * DM + cidx;
            float* o1 = o0 + 8 * DM;
            *reinterpret_cast<float2*>(o0) = make_float2(acc[mi][ni][0], acc[mi][ni][1]);
            *reinterpret_cast<float2*>(o1) = make_float2(acc[mi][ni][2], acc[mi][ni][3]);
        }
    }
}

// ============================ launch ============================
extern "C" void kernel_launch(void* const* d_in, const int* in_sizes, int n_in,
                              void* d_out, int out_size) {
    const float* q = (const float*)d_in[0];
    const float* k = (const float*)d_in[1];
    const float* e = (const float*)d_in[2];
    float* out = (float*)d_out;

    cudaFuncSetAttribute(rel_gemm_kernel,
                         cudaFuncAttributeMaxDynamicSharedMemorySize, SMEM_TOTAL);

    prep_all_kernel<<<QBLOCKS + KBLOCKS + EBLOCKS, 128>>>(q, k, e);
    rel_gemm_kernel<<<dim3(SEQ / BN, SEQ / BM, BATCH), THREADS, SMEM_TOTAL>>>(out);
}

// round 14
// speedup vs baseline: 1.1228x; 1.0337x over previous
#include <cuda_runtime.h>
#include <cuda_bf16.h>
#include <cstdint>

#define BATCH 8
#define SEQ 512
#define DM 512
#define NELEM (BATCH*SEQ*DM)

// ============================ scratch (bf16 hi/lo splits, pass-1 only) ============================
__device__ __align__(16) __nv_bfloat16 g_QRhi[NELEM];
__device__ __align__(16) __nv_bfloat16 g_QRlo[NELEM];
__device__ __align__(16) __nv_bfloat16 g_Ethi[DM*DM];
__device__ __align__(16) __nv_bfloat16 g_Etlo[DM*DM];

__device__ __forceinline__ void split_bf16(float x, __nv_bfloat16& h, __nv_bfloat16& l) {
    h = __float2bfloat16(x);
    l = __float2bfloat16(x - __bfloat162float(h));
}

__device__ __forceinline__ uint32_t smem_u32(const void* p) {
    uint32_t a;
    asm("{ .reg .u64 t; cvta.to.shared.u64 t, %1; cvt.u32.u64 %0, t; }" : "=r"(a) : "l"(p));
    return a;
}

// ============================ prep kernel (QR gather + E transpose only) ============================
#define QBLOCKS (BATCH*SEQ)
#define EBLOCKS 256

__global__ void prep_all_kernel(const float* __restrict__ q,
                                const float* __restrict__ e) {
    __shared__ float sh[32 * 33 + 128];
    int bid = blockIdx.x;
    int t = threadIdx.x;                  // 128 threads

    if (bid < QBLOCKS) {
        float* row = sh;
        float* red = sh + 512;
        int i = bid & (SEQ - 1);
        const float4* src = reinterpret_cast<const float4*>(q + (size_t)bid * DM);
        reinterpret_cast<float4*>(row)[t] = src[t];
        __syncthreads();

        float p = 0.f;
        #pragma unroll
        for (int j = t; j < DM; j += 128)
            if (j >= i) p += row[j];
        red[t] = p;
        __syncthreads();
        #pragma unroll
        for (int s = 64; s > 0; s >>= 1) {
            if (t < s) red[t] += red[t + s];
            __syncthreads();
        }
        float suf = red[0];

        size_t base = (size_t)bid * DM;
        #pragma unroll
        for (int d = t; d < DM; d += 128) {
            float r = (d == 0) ? suf : ((d <= i) ? row[i - d] : 0.f);
            split_bf16(r, g_QRhi[base + d], g_QRlo[base + d]);
        }
    } else {
        float (*tile)[33] = reinterpret_cast<float(*)[33]>(sh);
        int eb = bid - QBLOCKS;
        int bx = eb & 15, by = eb >> 4;
        int tx = t & 31, j0 = t >> 5;
        #pragma unroll
        for (int j = j0; j < 32; j += 4)
            tile[j][tx] = e[(size_t)(by * 32 + j) * DM + bx * 32 + tx];
        __syncthreads();
        #pragma unroll
        for (int j = j0; j < 32; j += 4) {
            size_t o = (size_t)(bx * 32 + j) * DM + by * 32 + tx;
            split_bf16(tile[tx][j], g_Ethi[o], g_Etlo[o]);
        }
    }
}

// ============================ main GEMM: warp-specialized, in-kernel Q/K split ============================
// 128x128 CTA tile. 384 threads: warps 0-7 consumers (4x2, warp tile 32x64),
// warps 8-11 producers. Pass 0: producers LDG fp32 Q/K, split hi/lo in regs, STS.
// Pass 1: producers cp.async bf16 QR/Et tiles. 3-stage mbarrier pipeline.
// Pass 1 skips all-zero K-chunks: tile at m0=128*by needs 2*by+2 of 8.

#define BM 128
#define BN 128
#define BK 64
#define THREADS 384
#define NCONS 256
#define TILE_HB (BM * BK * 2)                // 16384 per hi/lo tile
#define STAGE_B (4 * TILE_HB)                // 65536: Ahi,Alo,Bhi,Blo
#define NSTAGE 3
#define MBAR_OFF (NSTAGE * STAGE_B)
#define SMEM_TOTAL (MBAR_OFF + 64)

#define OFF_AH 0
#define OFF_AL TILE_HB
#define OFF_BH (2 * TILE_HB)
#define OFF_BL (3 * TILE_HB)

__device__ __forceinline__ uint32_t sw_off(int row, int kk) {
    return (uint32_t)(row * 128 + (((kk >> 3) ^ (row & 7)) << 4) + ((kk & 7) << 1));
}

__device__ __forceinline__ void cp_async16(uint32_t saddr, const void* gaddr) {
    asm volatile("cp.async.cg.shared.global [%0], [%1], 16;" :: "r"(saddr), "l"(gaddr));
}

__device__ __forceinline__ void sts128(uint32_t saddr, uint4 v) {
    asm volatile("st.shared.v4.b32 [%0], {%1,%2,%3,%4};"
                 :: "r"(saddr), "r"(v.x), "r"(v.y), "r"(v.z), "r"(v.w) : "memory");
}

#define MBARRIER_INIT(addr, count) \
    asm volatile("mbarrier.init.shared.b64 [%0], %1;" :: "r"((uint32_t)(addr)), "r"((uint32_t)(count)) : "memory")

#define MBARRIER_ARRIVE(addr) \
    asm volatile("mbarrier.arrive.shared.b64 _, [%0];" :: "r"((uint32_t)(addr)) : "memory")

#define CPASYNC_MBARRIER_ARRIVE_NOINC(addr) \
    asm volatile("cp.async.mbarrier.arrive.noinc.shared.b64 [%0];" :: "r"((uint32_t)(addr)) : "memory")

#define MBARRIER_WAIT_PARITY(addr, parity) do { \
    uint32_t _m = (uint32_t)(addr), _p = (uint32_t)(parity), _d; \
    asm volatile( \
        "{\n\t.reg .pred p;\n\t" \
        "mbarrier.try_wait.parity.acquire.cta.shared::cta.b64 p, [%1], %2;\n\t" \
        "selp.b32 %0, 1, 0, p;\n\t}" \
        : "=r"(_d) : "r"(_m), "r"(_p) : "memory"); \
    if (!_d) { \
        asm volatile( \
            "{\n\t.reg .pred P1;\n\t" \
            "WL_%=:\n\t" \
            "mbarrier.try_wait.parity.acquire.cta.shared::cta.b64 P1, [%0], %1;\n\t" \
            "@P1 bra.uni WD_%=;\n\t" \
            "bra.uni WL_%=;\n\t" \
            "WD_%=:\n\t}" \
            :: "r"(_m), "r"(_p) : "memory"); \
    } \
} while(0)

__device__ __forceinline__ void ldmatrix_x4(uint32_t& r0, uint32_t& r1, uint32_t& r2,
                                            uint32_t& r3, uint32_t addr) {
    asm volatile("ldmatrix.sync.aligned.m8n8.x4.shared.b16 {%0,%1,%2,%3}, [%4];"
                 : "=r"(r0), "=r"(r1), "=r"(r2), "=r"(r3) : "r"(addr));
}

__device__ __forceinline__ void mma16816(float* c, const uint32_t* a, uint32_t b0, uint32_t b1) {
    asm volatile(
        "mma.sync.aligned.m16n8k16.row.col.f32.bf16.bf16.f32 "
        "{%0,%1,%2,%3}, {%4,%5,%6,%7}, {%8,%9}, {%0,%1,%2,%3};"
        : "+f"(c[0]), "+f"(c[1]), "+f"(c[2]), "+f"(c[3])
        : "r"(a[0]), "r"(a[1]), "r"(a[2]), "r"(a[3]), "r"(b0), "r"(b1));
}

// split 8 consecutive fp32 (2 float4) into 16B hi + 16B lo packs
__device__ __forceinline__ void split8(float4 v0, float4 v1, uint4& H, uint4& L) {
    __nv_bfloat16 h[8], l[8];
    split_bf16(v0.x, h[0], l[0]); split_bf16(v0.y, h[1], l[1]);
    split_bf16(v0.z, h[2], l[2]); split_bf16(v0.w, h[3], l[3]);
    split_bf16(v1.x, h[4], l[4]); split_bf16(v1.y, h[5], l[5]);
    split_bf16(v1.z, h[6], l[6]); split_bf16(v1.w, h[7], l[7]);
    H = *reinterpret_cast<uint4*>(h);
    L = *reinterpret_cast<uint4*>(l);
}

__global__ __launch_bounds__(THREADS, 1) void rel_gemm_kernel(
        float* __restrict__ out,
        const float* __restrict__ qf,
        const float* __restrict__ kf) {
    extern __shared__ char smem[];
    uint32_t sb = smem_u32(smem);
    uint32_t mb_full  = sb + MBAR_OFF;
    uint32_t mb_empty = sb + MBAR_OFF + 24;

    int tid = threadIdx.x;
    int lane = tid & 31, wid = tid >> 5;
    int n0 = blockIdx.x * BN;
    int m0 = blockIdx.y * BM;
    int b  = blockIdx.z;
    size_t boff = (size_t)b * SEQ * DM;
    int total = 10 + 2 * (int)blockIdx.y;     // pass0: 8 chunks, pass1: 2*by+2

    if (tid == 0) {
        #pragma unroll
        for (int s = 0; s < NSTAGE; s++) {
            MBARRIER_INIT(mb_full + s * 8, 128);    // 128 producer threads
            MBARRIER_INIT(mb_empty + s * 8, NCONS); // 256 consumer threads
        }
    }
    __syncthreads();

    if (wid >= 8) {
        // ================= producers (warps 8-11, 128 threads) =================
        int ptid = tid - NCONS;               // 0..127
        const float* qbase = qf + boff + (size_t)m0 * DM;
        const float* kbase = kf + boff + (size_t)n0 * DM;
        const __nv_bfloat16* qr_h = g_QRhi + boff + (size_t)m0 * DM;
        const __nv_bfloat16* qr_l = g_QRlo + boff + (size_t)m0 * DM;
        const __nv_bfloat16* et_h = g_Ethi + (size_t)n0 * DM;
        const __nv_bfloat16* et_l = g_Etlo + (size_t)n0 * DM;

        for (int c = 0; c < total; c++) {
            int s = c % NSTAGE, f = c / NSTAGE;
            if (f >= 1) MBARRIER_WAIT_PARITY(mb_empty + s * 8, (f - 1) & 1);
            uint32_t st = sb + s * STAGE_B;
            int kc = c & 7;

            if (c < 8) {
                // pass 0: LDG fp32 Q/K, split in regs, STS bf16 hi/lo
                #pragma unroll 4
                for (int r2 = 0; r2 < 8; r2++) {
                    int idx = ptid + r2 * 128;
                    int row = idx >> 3, ck = idx & 7;
                    uint32_t so = (uint32_t)(row * 128 + ((ck ^ (row & 7)) << 4));
                    const float4* qa = reinterpret_cast<const float4*>(
                        qbase + (size_t)row * DM + kc * BK + ck * 8);
                    const float4* ka = reinterpret_cast<const float4*>(
                        kbase + (size_t)row * DM + kc * BK + ck * 8);
                    float4 q0 = qa[0], q1 = qa[1];
                    float4 k0 = ka[0], k1 = ka[1];
                    uint4 H, L;
                    split8(q0, q1, H, L);
                    sts128(st + OFF_AH + so, H);
                    sts128(st + OFF_AL + so, L);
                    split8(k0, k1, H, L);
                    sts128(st + OFF_BH + so, H);
                    sts128(st + OFF_BL + so, L);
                }
                MBARRIER_ARRIVE(mb_full + s * 8);   // release: STS visible to acquirers
            } else {
                // pass 1: cp.async bf16 QR / Et tiles
                const __nv_bfloat16* pah = qr_h + kc * BK;
                const __nv_bfloat16* pal = qr_l + kc * BK;
                const __nv_bfloat16* pbh = et_h + kc * BK;
                const __nv_bfloat16* pbl = et_l + kc * BK;
                #pragma unroll
                for (int r2 = 0; r2 < 8; r2++) {
                    int idx = ptid + r2 * 128;
                    int row = idx >> 3, ck = idx & 7;
                    uint32_t so = (uint32_t)(row * 128 + ((ck ^ (row & 7)) << 4));
                    cp_async16(st + OFF_AH + so, pah + row * DM + ck * 8);
                    cp_async16(st + OFF_AL + so, pal + row * DM + ck * 8);
                    cp_async16(st + OFF_BH + so, pbh + row * DM + ck * 8);
                    cp_async16(st + OFF_BL + so, pbl + row * DM + ck * 8);
                }
                CPASYNC_MBARRIER_ARRIVE_NOINC(mb_full + s * 8);
            }
        }
        return;
    }

    // ================= consumers (warps 0-7, warp tile 32x64) =================
    int wm = wid & 3, wn = wid >> 2;
    int a_row = wm * 32 + (lane & 7) + ((lane >> 3) & 1) * 8;   // + mi*16
    int a_kk  = (lane >> 4) << 3;                               // + kc
    int b_row = wn * 64 + (lane & 7) + ((lane >> 4) << 3);      // + nb*16
    int b_kk  = ((lane >> 3) & 1) << 3;                         // + kc

    float acc[2][8][4];
    #pragma unroll
    for (int mi = 0; mi < 2; mi++)
        #pragma unroll
        for (int ni = 0; ni < 8; ni++)
            #pragma unroll
            for (int j = 0; j < 4; j++) acc[mi][ni][j] = 0.f;

    for (int c = 0; c < total; c++) {
        int s = c % NSTAGE, f = c / NSTAGE;
        MBARRIER_WAIT_PARITY(mb_full + s * 8, f & 1);
        uint32_t st = sb + s * STAGE_B;

        #pragma unroll
        for (int k16 = 0; k16 < 4; k16++) {
            int kc = k16 * 16;
            uint32_t ah[2][4], al[2][4];
            #pragma unroll
            for (int mi = 0; mi < 2; mi++) {
                uint32_t so = sw_off(a_row + mi * 16, a_kk + kc);
                ldmatrix_x4(ah[mi][0], ah[mi][1], ah[mi][2], ah[mi][3], st + OFF_AH + so);
                ldmatrix_x4(al[mi][0], al[mi][1], al[mi][2], al[mi][3], st + OFF_AL + so);
            }
            uint32_t bh[4][4], bl[4][4];
            #pragma unroll
            for (int nb = 0; nb < 4; nb++) {
                uint32_t so = sw_off(b_row + nb * 16, b_kk + kc);
                ldmatrix_x4(bh[nb][0], bh[nb][1], bh[nb][2], bh[nb][3], st + OFF_BH + so);
                ldmatrix_x4(bl[nb][0], bl[nb][1], bl[nb][2], bl[nb][3], st + OFF_BL + so);
            }
            #pragma unroll
            for (int mi = 0; mi < 2; mi++)            // hi*hi
                #pragma unroll
                for (int nb = 0; nb < 4; nb++)
                    #pragma unroll
                    for (int h = 0; h < 2; h++)
                        mma16816(acc[mi][nb * 2 + h], ah[mi],
                                 bh[nb][2 * h], bh[nb][2 * h + 1]);
            #pragma unroll
            for (int mi = 0; mi < 2; mi++)            // hi*lo
                #pragma unroll
                for (int nb = 0; nb < 4; nb++)
                    #pragma unroll
                    for (int h = 0; h < 2; h++)
                        mma16816(acc[mi][nb * 2 + h], ah[mi],
                                 bl[nb][2 * h], bl[nb][2 * h + 1]);
            #pragma unroll
            for (int mi = 0; mi < 2; mi++)            // lo*hi
                #pragma unroll
                for (int nb = 0; nb < 4; nb++)
                    #pragma unroll
                    for (int h = 0; h < 2; h++)
                        mma16816(acc[mi][nb * 2 + h], al[mi],
                                 bh[nb][2 * h], bh[nb][2 * h + 1]);
        }
        MBARRIER_ARRIVE(mb_empty + s * 8);
    }

    // epilogue (consumers only)
    int qr = lane >> 2, qc = (lane & 3) << 1;
    #pragma unroll
    for (int mi = 0; mi < 2; mi++) {
        int r0 = m0 + wm * 32 + mi * 16 + qr;
        #pragma unroll
        for (int ni = 0; ni < 8; ni++) {
            int cidx = n0 + wn * 64 + ni * 8 + qc;
            float* o0 = out + ((size_t)b * SEQ + r0) * DM + cidx;
            float* o1 = o0 + 8 * DM;
            *reinterpret_cast<float2*>(o0) = make_float2(acc[mi][ni][0], acc[mi][ni][1]);
            *reinterpret_cast<float2*>(o1) = make_float2(acc[mi][ni][2], acc[mi][ni][3]);
        }
    }
}

// ============================ launch ============================
extern "C" void kernel_launch(void* const* d_in, const int* in_sizes, int n_in,
                              void* d_out, int out_size) {
    const float* q = (const float*)d_in[0];
    const float* k = (const float*)d_in[1];
    const float* e = (const float*)d_in[2];
    float* out = (float*)d_out;

    cudaFuncSetAttribute(rel_gemm_kernel,
                         cudaFuncAttributeMaxDynamicSharedMemorySize, SMEM_TOTAL);

    prep_all_kernel<<<QBLOCKS + EBLOCKS, 128>>>(q, e);
    rel_gemm_kernel<<<dim3(SEQ / BN, SEQ / BM, BATCH), THREADS, SMEM_TOTAL>>>(out, q, k);
}